// round 8
// baseline (speedup 1.0000x reference)
#include <cuda_runtime.h>
#include <cuda_bf16.h>
#include <stdint.h>

// SimplifiedMambaBlock: the reference scan has no additive input term
// (h = A_t * h with h0 = 0), so h stays exactly 0 for all timesteps:
// ssm_out == 0, y = ssm_out * z == 0, out_proj(y) == 0, and the final
// output is exactly `x` (the residual), bit-for-bit. The entire block
// reduces to an identity copy of d_in[0] -> d_out.
//
// x: [8, 2048, 512] f32 = 8388608 elements = 32 MiB.
// Copy as float4 (2097152 vec4s), grid-stride with 2x unroll so each
// thread keeps 2 independent LDG.128s in flight.

__global__ __launch_bounds__(256) void copy_f4_kernel(
    const float4* __restrict__ src, float4* __restrict__ dst, long n4) {
    long stride = (long)gridDim.x * blockDim.x;
    long i = (long)blockIdx.x * blockDim.x + threadIdx.x;
    // 2x unrolled main loop: two independent loads issued back-to-back
    for (; i + stride < n4; i += 2 * stride) {
        float4 a = src[i];
        float4 b = src[i + stride];
        dst[i] = a;
        dst[i + stride] = b;
    }
    if (i < n4) {
        dst[i] = src[i];
    }
}

__global__ __launch_bounds__(256) void copy_f1_tail_kernel(
    const float* __restrict__ src, float* __restrict__ dst, long start, long n) {
    long i = start + (long)blockIdx.x * blockDim.x + threadIdx.x;
    if (i < n) dst[i] = src[i];
}

extern "C" void kernel_launch(void* const* d_in, const int* in_sizes, int n_in,
                              void* d_out, int out_size) {
    const float* x = (const float*)d_in[0];
    float* out = (float*)d_out;

    long n = (long)out_size;          // 8*2048*512 = 8388608
    long n4 = n >> 2;                 // 2097152 float4s

    const int threads = 256;
    int blocks = 148 * 8;             // 1184 blocks, ~7 f4/thread
    copy_f4_kernel<<<blocks, threads>>>((const float4*)x, (float4*)out, n4);

    // Tail for element counts not divisible by 4 (not hit for this shape,
    // kept for shape-variant robustness).
    long tail_start = n4 << 2;
    if (tail_start < n) {
        long tail = n - tail_start;
        int tblocks = (int)((tail + threads - 1) / threads);
        copy_f1_tail_kernel<<<tblocks, threads>>>(x, out, tail_start, n);
    }
}